// round 8
// baseline (speedup 1.0000x reference)
#include <cuda_runtime.h>
#include <cstdint>

#define BB 2
#define LL 1024
#define DD 1024
#define NN 64
#define RR 64
#define KX 192               // R + 2N
#define MROWS (BB*LL)        // 2048
#define KSPL 8               // split-K factor for G3

// ---------------- scratch (device globals; no allocation) ----------------
__device__ __align__(256) float g_xn0 [MROWS*DD];
__device__ __align__(256) float g_xn1 [MROWS*DD];
__device__ __align__(256) float g_xn2 [MROWS*DD];
__device__ __align__(256) float g_xp  [MROWS*KX];
__device__ __align__(256) float g_delta[MROWS*DD];
__device__ __align__(256) float g_BC  [MROWS*2*NN];   // [m][0:64]=B*imp, [64:128]=C*imp
__device__ __align__(256) float g_y   [MROWS*DD];     // y + x*Dskip (tf32-rounded)
__device__ __align__(256) float g_A   [DD*NN];
__device__ __align__(256) float g_part[KSPL*MROWS*NN]; // split-K partials for G3
// tf32-rounded weights
__device__ __align__(256) float g_wWx  [KX*DD];
__device__ __align__(256) float g_wSel [DD*DD];
__device__ __align__(256) float g_wImp [NN*DD];
__device__ __align__(256) float g_wDt  [DD*RR];
__device__ __align__(256) float g_wGate[DD*DD];
__device__ __align__(256) float g_wOut [DD*DD];
__device__ int g_uniform = 1;   // statically 1; prep_k only ever clears it

// ---------------- tf32 helpers ----------------
__device__ __forceinline__ uint32_t f2tf32(float f) {
    uint32_t r;
    asm("cvt.rna.tf32.f32 %0, %1;" : "=r"(r) : "f"(f));
    return r;
}
__device__ __forceinline__ float rndtf(float f) { return __uint_as_float(f2tf32(f)); }

__device__ __forceinline__ void mma_tf32(float* d, const uint32_t* a, const uint32_t* b) {
    asm volatile(
        "mma.sync.aligned.m16n8k8.row.col.f32.tf32.tf32.f32 "
        "{%0,%1,%2,%3}, {%4,%5,%6,%7}, {%8,%9}, {%0,%1,%2,%3};"
        : "+f"(d[0]), "+f"(d[1]), "+f"(d[2]), "+f"(d[3])
        : "r"(a[0]), "r"(a[1]), "r"(a[2]), "r"(a[3]),
          "r"(b[0]), "r"(b[1]));
}

__device__ __forceinline__ void cpa16(uint32_t s, const void* g) {
    asm volatile("cp.async.cg.shared.global [%0], [%1], 16;" :: "r"(s), "l"(g));
}
#define CP_COMMIT() asm volatile("cp.async.commit_group;" ::: "memory")
#define CP_WAIT1()  asm volatile("cp.async.wait_group 1;"  ::: "memory")

// ---------------- unified prep: A matrix + all weight roundings ----------------
__global__ __launch_bounds__(256) void prep_k(
    const float* __restrict__ A_log,
    const float* __restrict__ Wx,   const float* __restrict__ selW,
    const float* __restrict__ impW, const float* __restrict__ dtW,
    const float* __restrict__ gateW,const float* __restrict__ Wout)
{
    const int nA4 = (DD*NN)/4;
    int i = blockIdx.x * blockDim.x + threadIdx.x;
    const int st = gridDim.x * blockDim.x;
    for (int idx = i; idx < nA4; idx += st) {
        float4 a = reinterpret_cast<const float4*>(A_log)[idx];
        float4 o;
        o.x = -__expf(a.x); o.y = -__expf(a.y);
        o.z = -__expf(a.z); o.w = -__expf(a.w);
        reinterpret_cast<float4*>(g_A)[idx] = o;
        if (a.x != 0.f || a.y != 0.f || a.z != 0.f || a.w != 0.f)
            g_uniform = 0;   // benign race (all writers store 0); monotone
    }
    const float* src[6] = {Wx, selW, impW, dtW, gateW, Wout};
    float* dst[6] = {g_wWx, g_wSel, g_wImp, g_wDt, g_wGate, g_wOut};
    const int n4[6] = {(KX*DD)/4, (DD*DD)/4, (NN*DD)/4, (DD*RR)/4, (DD*DD)/4, (DD*DD)/4};
    #pragma unroll
    for (int s = 0; s < 6; s++) {
        const float4* sp = reinterpret_cast<const float4*>(src[s]);
        float4* dp = reinterpret_cast<float4*>(dst[s]);
        for (int idx = i; idx < n4[s]; idx += st) {
            float4 v = sp[idx];
            v.x = rndtf(v.x); v.y = rndtf(v.y); v.z = rndtf(v.z); v.w = rndtf(v.w);
            dp[idx] = v;
        }
    }
}

// rmsnorm: one block per row m (2048 rows); output tf32-rounded
__global__ __launch_bounds__(256) void rms_k(const float* __restrict__ x,
                                             const float* __restrict__ nw) {
    int m = blockIdx.x;
    int tid = threadIdx.x;
    const float4* xr = reinterpret_cast<const float4*>(x + (size_t)m*DD);
    float4 v = xr[tid];
    float ss = v.x*v.x + v.y*v.y + v.z*v.z + v.w*v.w;
    #pragma unroll
    for (int o = 16; o > 0; o >>= 1) ss += __shfl_xor_sync(0xffffffffu, ss, o);
    __shared__ float sp[8];
    __shared__ float sscale;
    if ((tid & 31) == 0) sp[tid >> 5] = ss;
    __syncthreads();
    if (tid == 0) {
        float t = 0.f;
        #pragma unroll
        for (int i = 0; i < 8; i++) t += sp[i];
        sscale = rsqrtf(t * (1.0f/(float)DD) + 1e-6f);
    }
    __syncthreads();
    float sc = sscale;
    float4 w = reinterpret_cast<const float4*>(nw)[tid];
    float4 o;
    o.x = rndtf(v.x*sc*w.x); o.y = rndtf(v.y*sc*w.y);
    o.z = rndtf(v.z*sc*w.z); o.w = rndtf(v.w*sc*w.w);
    reinterpret_cast<float4*>(g_xn0 + (size_t)m*DD)[tid] = o;
}

// split-K reduce for G3: imp = sigmoid(sum partials + impb); g_BC = {B*imp, C*imp}
__global__ __launch_bounds__(256) void bcred_k(const float* __restrict__ impb) {
    int idx = blockIdx.x * blockDim.x + threadIdx.x;   // < MROWS*NN
    int m = idx >> 6, n = idx & 63;
    float s = 0.f;
    #pragma unroll
    for (int z = 0; z < KSPL; z++) s += g_part[z*(MROWS*NN) + idx];
    float sg = 1.f / (1.f + __expf(-(s + __ldg(impb + n))));
    const float* xpr = g_xp + (size_t)m*KX;
    g_BC[m*(2*NN) + n]      = xpr[RR + n]      * sg;
    g_BC[m*(2*NN) + NN + n] = xpr[RR + NN + n] * sg;
}

// ---------------- GEMM: C[M,N] = epi( A[M,K] @ W[N,K]^T ) ----------------
// tf32 mma.sync m16n8k8. Inputs pre-rounded to tf32 -> cp.async 3-stage pipeline,
// one __syncthreads per BK=16 iteration. BM=128, BN=64, 256 threads (8 warps 4m x 2n),
// warp tile 32x32 (2 x 4 mma tiles). SMEM [row][k] pad 20 -> conflict-free LDS.
// K = iteration extent (this CTA's chunk); Kld = W row stride (full K).
// gridDim.z > 1 => split-K: chunk z covers K-range [z*K, (z+1)*K), C += z*MROWS*ldc.
// EPI: 0 store, 1 sel-gate, 3 softplus, 4 gate.  RND: round stored C to tf32.
#define SKPAD 20

template<int EPI, int RND>
__global__ __launch_bounds__(256, 2) void gemm_k(
    const float* __restrict__ Aact, int lda,
    const float* __restrict__ W,
    float* __restrict__ C, int ldc, int K, int Kld,
    const float* __restrict__ bias,
    const float* __restrict__ gatev,
    const float* __restrict__ mulsrc)
{
    __shared__ uint32_t As[3][128*SKPAD];
    __shared__ uint32_t Bs[3][64*SKPAD];
    const int tid  = threadIdx.x;
    const int lane = tid & 31;
    const int wid  = tid >> 5;
    const int wm   = wid & 3;        // 0..3 (warp row)
    const int wn   = wid >> 2;       // 0..1 (warp col)
    const int g    = lane >> 2;      // 0..7
    const int t    = lane & 3;       // 0..3
    const int m0 = blockIdx.x * 128;
    const int n0 = blockIdx.y * 64;

    // split-K chunk offset
    {
        int kb0 = blockIdx.z * K;
        Aact += kb0;
        W    += kb0;
        C    += (size_t)blockIdx.z * MROWS * ldc;
    }

    float acc[2][4][4];
    #pragma unroll
    for (int mi = 0; mi < 2; mi++)
        #pragma unroll
        for (int ni = 0; ni < 4; ni++)
            #pragma unroll
            for (int j = 0; j < 4; j++) acc[mi][ni][j] = 0.f;

    const uint32_t sA = (uint32_t)__cvta_generic_to_shared(&As[0][0]);
    const uint32_t sB = (uint32_t)__cvta_generic_to_shared(&Bs[0][0]);
    const int lr  = tid >> 2;        // 0..63 row group
    const int lkq = tid & 3;         // float4 index along K

    auto aload = [&](int kb, int st) {
        #pragma unroll
        for (int i = 0; i < 2; i++) {
            int r = lr + i*64;
            cpa16(sA + (uint32_t)(st*(128*SKPAD) + r*SKPAD + lkq*4)*4u,
                  Aact + (size_t)(m0 + r)*lda + kb*16 + lkq*4);
        }
        cpa16(sB + (uint32_t)(st*(64*SKPAD) + lr*SKPAD + lkq*4)*4u,
              W + (size_t)(n0 + lr)*Kld + kb*16 + lkq*4);
        CP_COMMIT();
    };

    const int nkb = K >> 4;          // >= 4 for all call sites
    aload(0, 0);
    aload(1, 1);

    for (int kb = 0; kb < nkb; ++kb) {
        CP_WAIT1();                  // group kb complete (youngest outstanding = kb+1)
        __syncthreads();             // publish; all threads done with buffer (kb-1)%3
        if (kb + 2 < nkb) aload(kb + 2, (kb + 2) % 3);
        else              CP_COMMIT();   // empty group keeps wait-count invariant
        const int cur = kb % 3;
        #pragma unroll
        for (int ks = 0; ks < 2; ++ks) {
            const int k = ks*8 + t;
            uint32_t af[2][4], bf[4][2];
            #pragma unroll
            for (int mi = 0; mi < 2; mi++) {
                int row = wm*32 + mi*16 + g;
                af[mi][0] = As[cur][row*SKPAD + k];
                af[mi][1] = As[cur][(row+8)*SKPAD + k];
                af[mi][2] = As[cur][row*SKPAD + k + 4];
                af[mi][3] = As[cur][(row+8)*SKPAD + k + 4];
            }
            #pragma unroll
            for (int ni = 0; ni < 4; ni++) {
                int col = wn*32 + ni*8 + g;
                bf[ni][0] = Bs[cur][col*SKPAD + k];
                bf[ni][1] = Bs[cur][col*SKPAD + k + 4];
            }
            #pragma unroll
            for (int mi = 0; mi < 2; mi++)
                #pragma unroll
                for (int ni = 0; ni < 4; ni++)
                    mma_tf32(acc[mi][ni], af[mi], bf[ni]);
        }
    }

    // ---- epilogue ----
    // thread owns rows (wm*32 + mi*16 + g) and (+8); cols (wn*32 + ni*8 + 2t, +1)
    float bn[4][2], gnv[4][2];
    if (EPI != 0) {
        #pragma unroll
        for (int ni = 0; ni < 4; ni++) {
            int n = n0 + wn*32 + ni*8 + 2*t;
            bn[ni][0] = __ldg(bias + n); bn[ni][1] = __ldg(bias + n + 1);
            if (EPI == 1) { gnv[ni][0] = __ldg(gatev + n); gnv[ni][1] = __ldg(gatev + n + 1); }
        }
    }

    #pragma unroll
    for (int mi = 0; mi < 2; mi++) {
        #pragma unroll
        for (int half = 0; half < 2; half++) {    // half 0: rows g, half 1: rows g+8
            int m = m0 + wm*32 + mi*16 + g + half*8;
            #pragma unroll
            for (int ni = 0; ni < 4; ni++) {
                int cl = wn*32 + ni*8 + 2*t;      // local col within BN
                float v0 = acc[mi][ni][half*2 + 0];
                float v1 = acc[mi][ni][half*2 + 1];
                if (EPI == 1 || EPI == 4) {
                    float2 ms = *reinterpret_cast<const float2*>(
                        mulsrc + (size_t)m*DD + n0 + cl);
                    float u0 = (EPI == 1) ? (v0 + bn[ni][0]) * gnv[ni][0] : (v0 + bn[ni][0]);
                    float u1 = (EPI == 1) ? (v1 + bn[ni][1]) * gnv[ni][1] : (v1 + bn[ni][1]);
                    v0 = ms.x * (1.f / (1.f + __expf(-u0)));
                    v1 = ms.y * (1.f / (1.f + __expf(-u1)));
                } else if (EPI == 3) {
                    float u0 = v0 + bn[ni][0];
                    float u1 = v1 + bn[ni][1];
                    v0 = (u0 > 20.f) ? u0 : log1pf(__expf(u0));
                    v1 = (u1 > 20.f) ? u1 : log1pf(__expf(u1));
                }
                if (RND) { v0 = rndtf(v0); v1 = rndtf(v1); }
                *reinterpret_cast<float2*>(C + (size_t)m*ldc + n0 + cl) = make_float2(v0, v1);
            }
        }
    }
}

// ---------------- selective scan ----------------
// grid (D/8, B), block 128: 8 d's per block, 16 lanes per d, 4 n-states per lane.
// depth-8 register prefetch (lead ~>= L2 latency); exp off the h critical path.
// y output tf32-rounded (feeds G6).
struct Raw { float dt, xv, xo; float4 Bv, Cv; };

template<bool UNI>
__device__ __forceinline__ void scan_impl(int b, int dg, int q,
                                          const float* __restrict__ x_in,
                                          float dsk, const float* Areg)
{
    const size_t base = (size_t)b*LL*DD + dg;
    const float* dptr  = g_delta + base;
    const float* xptr  = g_xn2   + base;
    const float* xoptr = x_in    + base;
    const float* bcptr = g_BC + (size_t)b*LL*(2*NN) + q*4;
    float* yo = g_y + base;

    float h0 = 0.f, h1 = 0.f, h2 = 0.f, h3 = 0.f;
    Raw r[8];

    auto LDR = [&](int t, Raw& rr) {
        int o = t * DD;
        rr.dt = __ldg(dptr + o);
        rr.xv = __ldg(xptr + o);
        rr.xo = __ldg(xoptr + o);
        const float* bc = bcptr + t * (2*NN);
        rr.Bv = __ldg(reinterpret_cast<const float4*>(bc));
        rr.Cv = __ldg(reinterpret_cast<const float4*>(bc + NN));
    };

    auto STEP = [&](int t, Raw& rr) {
        float e0, e1, e2, e3;
        if (UNI) {
            float e = __expf(-rr.dt);
            e0 = e; e1 = e; e2 = e; e3 = e;
        } else {
            e0 = __expf(rr.dt * Areg[0]); e1 = __expf(rr.dt * Areg[1]);
            e2 = __expf(rr.dt * Areg[2]); e3 = __expf(rr.dt * Areg[3]);
        }
        float c = rr.dt * rr.xv;
        h0 = fmaf(e0, h0, c * rr.Bv.x);
        h1 = fmaf(e1, h1, c * rr.Bv.y);
        h2 = fmaf(e2, h2, c * rr.Bv.z);
        h3 = fmaf(e3, h3, c * rr.Bv.w);
        float yp = fmaf(h0, rr.Cv.x, fmaf(h1, rr.Cv.y, fmaf(h2, rr.Cv.z, h3 * rr.Cv.w)));
        yp += __shfl_xor_sync(0xffffffffu, yp, 1);
        yp += __shfl_xor_sync(0xffffffffu, yp, 2);
        yp += __shfl_xor_sync(0xffffffffu, yp, 4);
        yp += __shfl_xor_sync(0xffffffffu, yp, 8);
        if (q == 0) yo[t*DD] = rndtf(yp + rr.xo * dsk);
    };

    #pragma unroll
    for (int j = 0; j < 8; j++) LDR(j, r[j]);
    for (int t = 0; t < LL; t += 8) {
        #pragma unroll
        for (int j = 0; j < 8; j++) {
            STEP(t + j, r[j]);
            if (t + j + 8 < LL) LDR(t + j + 8, r[j]);
        }
    }
}

__global__ __launch_bounds__(128) void scan_k(const float* __restrict__ x_in,
                                              const float* __restrict__ Dskip)
{
    int b  = blockIdx.y;
    int dl = threadIdx.x >> 4;       // 0..7
    int q  = threadIdx.x & 15;       // 0..15
    int dg = blockIdx.x * 8 + dl;
    float dsk = Dskip[dg];
    float Areg[4] = {0.f, 0.f, 0.f, 0.f};
    bool uni = (g_uniform != 0);
    if (!uni) {
        #pragma unroll
        for (int i = 0; i < 4; i++) Areg[i] = g_A[dg*NN + q*4 + i];
    }
    if (uni) scan_impl<true >(b, dg, q, x_in, dsk, Areg);
    else     scan_impl<false>(b, dg, q, x_in, dsk, Areg);
}

// ---------------- launch ----------------
extern "C" void kernel_launch(void* const* d_in, const int* in_sizes, int n_in,
                              void* d_out, int out_size)
{
    (void)in_sizes; (void)n_in; (void)out_size;
    const float* x        = (const float*)d_in[0];
    const float* norm_w   = (const float*)d_in[1];
    const float* Wx       = (const float*)d_in[2];
    const float* dtW      = (const float*)d_in[3];
    const float* dtb      = (const float*)d_in[4];
    const float* A_log    = (const float*)d_in[5];
    const float* Dskip    = (const float*)d_in[6];
    const float* Wout     = (const float*)d_in[7];
    const float* selW     = (const float*)d_in[8];
    const float* selb     = (const float*)d_in[9];
    const float* sel_gate = (const float*)d_in[10];
    const float* impW     = (const float*)d_in[11];
    const float* impb     = (const float*)d_in[12];
    const float* gateW    = (const float*)d_in[13];
    const float* gateb    = (const float*)d_in[14];
    float* out = (float*)d_out;

    float *p_xn0, *p_xn1, *p_xn2, *p_xp, *p_delta, *p_y, *p_part;
    float *p_wWx, *p_wSel, *p_wImp, *p_wDt, *p_wGate, *p_wOut;
    cudaGetSymbolAddress((void**)&p_xn0,  g_xn0);
    cudaGetSymbolAddress((void**)&p_xn1,  g_xn1);
    cudaGetSymbolAddress((void**)&p_xn2,  g_xn2);
    cudaGetSymbolAddress((void**)&p_xp,   g_xp);
    cudaGetSymbolAddress((void**)&p_delta,g_delta);
    cudaGetSymbolAddress((void**)&p_y,    g_y);
    cudaGetSymbolAddress((void**)&p_part, g_part);
    cudaGetSymbolAddress((void**)&p_wWx,  g_wWx);
    cudaGetSymbolAddress((void**)&p_wSel, g_wSel);
    cudaGetSymbolAddress((void**)&p_wImp, g_wImp);
    cudaGetSymbolAddress((void**)&p_wDt,  g_wDt);
    cudaGetSymbolAddress((void**)&p_wGate,g_wGate);
    cudaGetSymbolAddress((void**)&p_wOut, g_wOut);

    // unified prep: A matrix + all tf32 weight roundings (one launch)
    prep_k<<<148, 256>>>(A_log, Wx, selW, impW, dtW, gateW, Wout);
    rms_k<<<MROWS, 256>>>(x, norm_w);

    // G1: xp = xn0 @ Wx^T                         [2048 x 192, K=1024] (rounded out)
    gemm_k<0,1><<<dim3(16, 3), 256>>>(p_xn0, DD, p_wWx, p_xp, KX, DD, DD,
                                      nullptr, nullptr, nullptr);
    // G2: xn1 = xn0 * sigmoid((xn0@selW^T + selb)*sel_gate)   (rounded out)
    gemm_k<1,1><<<dim3(16, 16), 256>>>(p_xn0, DD, p_wSel, p_xn1, DD, DD, DD,
                                       selb, sel_gate, p_xn0);
    // G3: imp partials (split-K x8): g_part[z] = xn1 @ impW^T over K-chunk z
    gemm_k<0,0><<<dim3(16, 1, KSPL), 256>>>(p_xn1, DD, p_wImp, p_part, NN,
                                            DD/KSPL, DD, nullptr, nullptr, nullptr);
    // reduce + sigmoid + fused BC scaling
    bcred_k<<<(MROWS*NN)/256, 256>>>(impb);
    // G4: delta = softplus(delta_r @ dtW^T + dtb) [K=64]
    gemm_k<3,0><<<dim3(16, 16), 256>>>(p_xp, KX, p_wDt, p_delta, DD, RR, RR,
                                       dtb, nullptr, nullptr);
    // G5: xn2 = xn1 * sigmoid(xn1@gateW^T + gateb)
    gemm_k<4,0><<<dim3(16, 16), 256>>>(p_xn1, DD, p_wGate, p_xn2, DD, DD, DD,
                                       gateb, nullptr, p_xn1);
    // selective scan -> g_y = round_tf32(y + x*Dskip)
    scan_k<<<dim3(DD/8, BB), 128>>>(x, Dskip);
    // G6: out = g_y @ Wout^T
    gemm_k<0,0><<<dim3(16, 16), 256>>>(p_y, DD, p_wOut, out, DD, DD, DD,
                                       nullptr, nullptr, nullptr);
}

// round 17
// speedup vs baseline: 1.0388x; 1.0388x over previous
#include <cuda_runtime.h>
#include <cstdint>

#define BB 2
#define LL 1024
#define DD 1024
#define NN 64
#define RR 64
#define KX 192               // R + 2N
#define MROWS (BB*LL)        // 2048
#define KSPL 8               // split-K factor for G3

// ---------------- scratch (device globals; no allocation) ----------------
__device__ __align__(256) float g_xn0 [MROWS*DD];
__device__ __align__(256) float g_xn1 [MROWS*DD];
__device__ __align__(256) float g_xn2 [MROWS*DD];
__device__ __align__(256) float g_xp  [MROWS*KX];
__device__ __align__(256) float g_delta[MROWS*DD];
__device__ __align__(256) float g_BC  [MROWS*2*NN];   // [m][0:64]=B*imp, [64:128]=C*imp
__device__ __align__(256) float g_y   [MROWS*DD];     // y + x*Dskip (tf32-rounded)
__device__ __align__(256) float g_A   [DD*NN];
__device__ __align__(256) float g_part[KSPL*MROWS*NN]; // split-K partials for G3
// tf32-rounded weights
__device__ __align__(256) float g_wWx  [KX*DD];
__device__ __align__(256) float g_wSel [DD*DD];
__device__ __align__(256) float g_wImp [NN*DD];
__device__ __align__(256) float g_wDt  [DD*RR];
__device__ __align__(256) float g_wGate[DD*DD];
__device__ __align__(256) float g_wOut [DD*DD];
__device__ int g_uniform = 1;   // statically 1; prep path only ever clears it

// ---------------- tf32 helpers ----------------
__device__ __forceinline__ uint32_t f2tf32(float f) {
    uint32_t r;
    asm("cvt.rna.tf32.f32 %0, %1;" : "=r"(r) : "f"(f));
    return r;
}
__device__ __forceinline__ float rndtf(float f) { return __uint_as_float(f2tf32(f)); }

__device__ __forceinline__ void mma_tf32(float* d, const uint32_t* a, const uint32_t* b) {
    asm volatile(
        "mma.sync.aligned.m16n8k8.row.col.f32.tf32.tf32.f32 "
        "{%0,%1,%2,%3}, {%4,%5,%6,%7}, {%8,%9}, {%0,%1,%2,%3};"
        : "+f"(d[0]), "+f"(d[1]), "+f"(d[2]), "+f"(d[3])
        : "r"(a[0]), "r"(a[1]), "r"(a[2]), "r"(a[3]),
          "r"(b[0]), "r"(b[1]));
}

__device__ __forceinline__ void cpa16(uint32_t s, const void* g) {
    asm volatile("cp.async.cg.shared.global [%0], [%1], 16;" :: "r"(s), "l"(g));
}
#define CP_COMMIT() asm volatile("cp.async.commit_group;" ::: "memory")
#define CP_WAIT1()  asm volatile("cp.async.wait_group 1;"  ::: "memory")

// ---------------- merged rmsnorm + prep ----------------
// blocks [0, MROWS): rmsnorm row m (tf32-rounded out)
// blocks [MROWS, MROWS+148): A matrix prep + tf32 weight roundings (grid-stride)
__global__ __launch_bounds__(256) void prerms_k(
    const float* __restrict__ x,    const float* __restrict__ nw,
    const float* __restrict__ A_log,
    const float* __restrict__ Wx,   const float* __restrict__ selW,
    const float* __restrict__ impW, const float* __restrict__ dtW,
    const float* __restrict__ gateW,const float* __restrict__ Wout)
{
    const int bid = blockIdx.x;
    const int tid = threadIdx.x;
    if (bid < MROWS) {
        // ---- rmsnorm ----
        const int m = bid;
        const float4* xr = reinterpret_cast<const float4*>(x + (size_t)m*DD);
        float4 v = xr[tid];
        float ss = v.x*v.x + v.y*v.y + v.z*v.z + v.w*v.w;
        #pragma unroll
        for (int o = 16; o > 0; o >>= 1) ss += __shfl_xor_sync(0xffffffffu, ss, o);
        __shared__ float sp[8];
        __shared__ float sscale;
        if ((tid & 31) == 0) sp[tid >> 5] = ss;
        __syncthreads();
        if (tid == 0) {
            float t = 0.f;
            #pragma unroll
            for (int i = 0; i < 8; i++) t += sp[i];
            sscale = rsqrtf(t * (1.0f/(float)DD) + 1e-6f);
        }
        __syncthreads();
        float sc = sscale;
        float4 w = reinterpret_cast<const float4*>(nw)[tid];
        float4 o;
        o.x = rndtf(v.x*sc*w.x); o.y = rndtf(v.y*sc*w.y);
        o.z = rndtf(v.z*sc*w.z); o.w = rndtf(v.w*sc*w.w);
        reinterpret_cast<float4*>(g_xn0 + (size_t)m*DD)[tid] = o;
    } else {
        // ---- prep (148 blocks, grid-stride) ----
        const int i  = (bid - MROWS) * 256 + tid;
        const int st = 148 * 256;
        const int nA4 = (DD*NN)/4;
        for (int idx = i; idx < nA4; idx += st) {
            float4 a = reinterpret_cast<const float4*>(A_log)[idx];
            float4 o;
            o.x = -__expf(a.x); o.y = -__expf(a.y);
            o.z = -__expf(a.z); o.w = -__expf(a.w);
            reinterpret_cast<float4*>(g_A)[idx] = o;
            if (a.x != 0.f || a.y != 0.f || a.z != 0.f || a.w != 0.f)
                g_uniform = 0;   // benign race (all writers store 0); monotone
        }
        const float* src[6] = {Wx, selW, impW, dtW, gateW, Wout};
        float* dst[6] = {g_wWx, g_wSel, g_wImp, g_wDt, g_wGate, g_wOut};
        const int n4[6] = {(KX*DD)/4, (DD*DD)/4, (NN*DD)/4, (DD*RR)/4, (DD*DD)/4, (DD*DD)/4};
        #pragma unroll
        for (int s = 0; s < 6; s++) {
            const float4* sp4 = reinterpret_cast<const float4*>(src[s]);
            float4* dp = reinterpret_cast<float4*>(dst[s]);
            for (int idx = i; idx < n4[s]; idx += st) {
                float4 v = sp4[idx];
                v.x = rndtf(v.x); v.y = rndtf(v.y); v.z = rndtf(v.z); v.w = rndtf(v.w);
                dp[idx] = v;
            }
        }
    }
}

// split-K reduce for G3: imp = sigmoid(sum partials + impb); g_BC = {B*imp, C*imp}
__global__ __launch_bounds__(256) void bcred_k(const float* __restrict__ impb) {
    int idx = blockIdx.x * blockDim.x + threadIdx.x;   // < MROWS*NN
    int m = idx >> 6, n = idx & 63;
    float s = 0.f;
    #pragma unroll
    for (int z = 0; z < KSPL; z++) s += g_part[z*(MROWS*NN) + idx];
    float sg = 1.f / (1.f + __expf(-(s + __ldg(impb + n))));
    const float* xpr = g_xp + (size_t)m*KX;
    g_BC[m*(2*NN) + n]      = xpr[RR + n]      * sg;
    g_BC[m*(2*NN) + NN + n] = xpr[RR + NN + n] * sg;
}

// ---------------- GEMM core: C[M,N] = epi( A[M,K] @ W[N,K]^T ) ----------------
// tf32 mma.sync m16n8k8. Inputs pre-rounded to tf32 -> cp.async 3-stage pipeline,
// one __syncthreads per BK=16 iteration. BM=128, BN=64, 512 threads (16 warps 4m x 4n),
// warp tile 32x16 (2 x 2 mma tiles). SMEM [row][k] pad 20 -> conflict-free LDS.
// K = iteration extent (this call's chunk); Kld = W row stride (full K).
// zc > 0 => split-K: chunk zc covers K-range [zc*K,(zc+1)*K), C += zc*MROWS*ldc.
// EPI: 0 store, 1 sel-gate, 3 softplus, 4 gate.  RND: round stored C to tf32.
#define SKPAD 20
#define GT 512

template<int EPI, int RND>
__device__ __forceinline__ void gemm_core(
    uint32_t* __restrict__ As,           // [3*128*SKPAD] shared
    uint32_t* __restrict__ Bs,           // [3*64*SKPAD] shared
    const float* __restrict__ Aact, int lda,
    const float* __restrict__ W,
    float* __restrict__ C, int ldc, int K, int Kld, int zc, int m0, int n0,
    const float* __restrict__ bias,
    const float* __restrict__ gatev,
    const float* __restrict__ mulsrc)
{
    const int tid  = threadIdx.x;
    const int lane = tid & 31;
    const int wid  = tid >> 5;       // 0..15
    const int wm   = wid & 3;        // 0..3 (warp row, 32 rows each)
    const int wn   = wid >> 2;       // 0..3 (warp col, 16 cols each)
    const int g    = lane >> 2;      // 0..7
    const int t    = lane & 3;       // 0..3

    // split-K chunk offset
    {
        int kb0 = zc * K;
        Aact += kb0;
        W    += kb0;
        C    += (size_t)zc * MROWS * ldc;
    }

    float acc[2][2][4];
    #pragma unroll
    for (int mi = 0; mi < 2; mi++)
        #pragma unroll
        for (int ni = 0; ni < 2; ni++)
            #pragma unroll
            for (int j = 0; j < 4; j++) acc[mi][ni][j] = 0.f;

    const uint32_t sA = (uint32_t)__cvta_generic_to_shared(As);
    const uint32_t sB = (uint32_t)__cvta_generic_to_shared(Bs);
    const int lr  = tid >> 2;        // 0..127 (A row); B row when < 64
    const int lkq = tid & 3;         // float4 index along K

    // per-iteration loads: A 128x16 (1 x 16B per thread), B 64x16 (threads 0..255)
    auto aload = [&](int kb, int st) {
        cpa16(sA + (uint32_t)(st*(128*SKPAD) + lr*SKPAD + lkq*4)*4u,
              Aact + (size_t)(m0 + lr)*lda + kb*16 + lkq*4);
        if (lr < 64)
            cpa16(sB + (uint32_t)(st*(64*SKPAD) + lr*SKPAD + lkq*4)*4u,
                  W + (size_t)(n0 + lr)*Kld + kb*16 + lkq*4);
        CP_COMMIT();
    };

    const int nkb = K >> 4;          // >= 4 for all call sites
    aload(0, 0);
    aload(1, 1);

    for (int kb = 0; kb < nkb; ++kb) {
        CP_WAIT1();                  // group kb complete (youngest outstanding = kb+1)
        __syncthreads();             // publish; all threads done with buffer (kb-1)%3
        if (kb + 2 < nkb) aload(kb + 2, (kb + 2) % 3);
        else              CP_COMMIT();   // empty group keeps wait-count invariant
        const int cur = kb % 3;
        #pragma unroll
        for (int ks = 0; ks < 2; ++ks) {
            const int k = ks*8 + t;
            uint32_t af[2][4], bf[2][2];
            #pragma unroll
            for (int mi = 0; mi < 2; mi++) {
                int row = wm*32 + mi*16 + g;
                af[mi][0] = As[cur*(128*SKPAD) + row*SKPAD + k];
                af[mi][1] = As[cur*(128*SKPAD) + (row+8)*SKPAD + k];
                af[mi][2] = As[cur*(128*SKPAD) + row*SKPAD + k + 4];
                af[mi][3] = As[cur*(128*SKPAD) + (row+8)*SKPAD + k + 4];
            }
            #pragma unroll
            for (int ni = 0; ni < 2; ni++) {
                int col = wn*16 + ni*8 + g;
                bf[ni][0] = Bs[cur*(64*SKPAD) + col*SKPAD + k];
                bf[ni][1] = Bs[cur*(64*SKPAD) + col*SKPAD + k + 4];
            }
            #pragma unroll
            for (int mi = 0; mi < 2; mi++)
                #pragma unroll
                for (int ni = 0; ni < 2; ni++)
                    mma_tf32(acc[mi][ni], af[mi], bf[ni]);
        }
    }

    // ---- epilogue ----
    // thread owns rows (wm*32 + mi*16 + g) and (+8); cols (wn*16 + ni*8 + 2t, +1)
    float bn[2][2], gnv[2][2];
    if (EPI != 0) {
        #pragma unroll
        for (int ni = 0; ni < 2; ni++) {
            int n = n0 + wn*16 + ni*8 + 2*t;
            bn[ni][0] = __ldg(bias + n); bn[ni][1] = __ldg(bias + n + 1);
            if (EPI == 1) { gnv[ni][0] = __ldg(gatev + n); gnv[ni][1] = __ldg(gatev + n + 1); }
        }
    }

    #pragma unroll
    for (int mi = 0; mi < 2; mi++) {
        #pragma unroll
        for (int half = 0; half < 2; half++) {    // half 0: rows g, half 1: rows g+8
            int m = m0 + wm*32 + mi*16 + g + half*8;
            #pragma unroll
            for (int ni = 0; ni < 2; ni++) {
                int cl = wn*16 + ni*8 + 2*t;      // local col within BN
                float v0 = acc[mi][ni][half*2 + 0];
                float v1 = acc[mi][ni][half*2 + 1];
                if (EPI == 1 || EPI == 4) {
                    float2 ms = *reinterpret_cast<const float2*>(
                        mulsrc + (size_t)m*DD + n0 + cl);
                    float u0 = (EPI == 1) ? (v0 + bn[ni][0]) * gnv[ni][0] : (v0 + bn[ni][0]);
                    float u1 = (EPI == 1) ? (v1 + bn[ni][1]) * gnv[ni][1] : (v1 + bn[ni][1]);
                    v0 = ms.x * (1.f / (1.f + __expf(-u0)));
                    v1 = ms.y * (1.f / (1.f + __expf(-u1)));
                } else if (EPI == 3) {
                    float u0 = v0 + bn[ni][0];
                    float u1 = v1 + bn[ni][1];
                    v0 = (u0 > 20.f) ? u0 : log1pf(__expf(u0));
                    v1 = (u1 > 20.f) ? u1 : log1pf(__expf(u1));
                }
                if (RND) { v0 = rndtf(v0); v1 = rndtf(v1); }
                *reinterpret_cast<float2*>(C + (size_t)m*ldc + n0 + cl) = make_float2(v0, v1);
            }
        }
    }
}

// merged G1+G2: by<3 -> xp = xn0 @ Wx^T (rounded); else xn1 = sel-gate(xn0 @ selW^T)
__global__ __launch_bounds__(GT, 2) void gemm12_k(
    const float* __restrict__ xn0, const float* __restrict__ wWx,
    const float* __restrict__ wSel, float* __restrict__ xp, float* __restrict__ xn1,
    const float* __restrict__ selb, const float* __restrict__ sel_gate)
{
    __shared__ uint32_t As[3*128*SKPAD];
    __shared__ uint32_t Bs[3*64*SKPAD];
    const int m0 = blockIdx.x * 128;
    const int by = blockIdx.y;
    if (by < 3) {
        gemm_core<0,1>(As, Bs, xn0, DD, wWx, xp, KX, DD, DD, 0, m0, by*64,
                       nullptr, nullptr, nullptr);
    } else {
        gemm_core<1,1>(As, Bs, xn0, DD, wSel, xn1, DD, DD, DD, 0, m0, (by-3)*64,
                       selb, sel_gate, xn0);
    }
}

// merged G5+G4+G3: by<16 -> gate GEMM; by<32 -> softplus/delta; else G3 split-K partials
__global__ __launch_bounds__(GT, 2) void gemm345_k(
    const float* __restrict__ xn1, const float* __restrict__ xp,
    const float* __restrict__ wGate, const float* __restrict__ wDt,
    const float* __restrict__ wImp,
    float* __restrict__ xn2, float* __restrict__ delta, float* __restrict__ part,
    const float* __restrict__ gateb, const float* __restrict__ dtb)
{
    __shared__ uint32_t As[3*128*SKPAD];
    __shared__ uint32_t Bs[3*64*SKPAD];
    const int m0 = blockIdx.x * 128;
    const int by = blockIdx.y;
    if (by < 16) {
        gemm_core<4,0>(As, Bs, xn1, DD, wGate, xn2, DD, DD, DD, 0, m0, by*64,
                       gateb, nullptr, xn1);
    } else if (by < 32) {
        gemm_core<3,0>(As, Bs, xp, KX, wDt, delta, DD, RR, RR, 0, m0, (by-16)*64,
                       dtb, nullptr, nullptr);
    } else {
        gemm_core<0,0>(As, Bs, xn1, DD, wImp, part, NN, DD/KSPL, DD, by-32, m0, 0,
                       nullptr, nullptr, nullptr);
    }
}

// G6: out = y @ Wout^T
__global__ __launch_bounds__(GT, 2) void gemm6_k(
    const float* __restrict__ y, const float* __restrict__ wOut, float* __restrict__ out)
{
    __shared__ uint32_t As[3*128*SKPAD];
    __shared__ uint32_t Bs[3*64*SKPAD];
    gemm_core<0,0>(As, Bs, y, DD, wOut, out, DD, DD, DD, 0,
                   blockIdx.x*128, blockIdx.y*64, nullptr, nullptr, nullptr);
}

// ---------------- selective scan ----------------
// grid (D/8, B), block 128: 8 d's per block, 16 lanes per d, 4 n-states per lane.
// depth-8 register prefetch (lead ~>= L2 latency); exp off the h critical path.
// y output tf32-rounded (feeds G6).
struct Raw { float dt, xv, xo; float4 Bv, Cv; };

template<bool UNI>
__device__ __forceinline__ void scan_impl(int b, int dg, int q,
                                          const float* __restrict__ x_in,
                                          float dsk, const float* Areg)
{
    const size_t base = (size_t)b*LL*DD + dg;
    const float* dptr  = g_delta + base;
    const float* xptr  = g_xn2   + base;
    const float* xoptr = x_in    + base;
    const float* bcptr = g_BC + (size_t)b*LL*(2*NN) + q*4;
    float* yo = g_y + base;

    float h0 = 0.f, h1 = 0.f, h2 = 0.f, h3 = 0.f;
    Raw r[8];

    auto LDR = [&](int t, Raw& rr) {
        int o = t * DD;
        rr.dt = __ldg(dptr + o);
        rr.xv = __ldg(xptr + o);
        rr.xo = __ldg(xoptr + o);
        const float* bc = bcptr + t * (2*NN);
        rr.Bv = __ldg(reinterpret_cast<const float4*>(bc));
        rr.Cv = __ldg(reinterpret_cast<const float4*>(bc + NN));
    };

    auto STEP = [&](int t, Raw& rr) {
        float e0, e1, e2, e3;
        if (UNI) {
            float e = __expf(-rr.dt);
            e0 = e; e1 = e; e2 = e; e3 = e;
        } else {
            e0 = __expf(rr.dt * Areg[0]); e1 = __expf(rr.dt * Areg[1]);
            e2 = __expf(rr.dt * Areg[2]); e3 = __expf(rr.dt * Areg[3]);
        }
        float c = rr.dt * rr.xv;
        h0 = fmaf(e0, h0, c * rr.Bv.x);
        h1 = fmaf(e1, h1, c * rr.Bv.y);
        h2 = fmaf(e2, h2, c * rr.Bv.z);
        h3 = fmaf(e3, h3, c * rr.Bv.w);
        float yp = fmaf(h0, rr.Cv.x, fmaf(h1, rr.Cv.y, fmaf(h2, rr.Cv.z, h3 * rr.Cv.w)));
        yp += __shfl_xor_sync(0xffffffffu, yp, 1);
        yp += __shfl_xor_sync(0xffffffffu, yp, 2);
        yp += __shfl_xor_sync(0xffffffffu, yp, 4);
        yp += __shfl_xor_sync(0xffffffffu, yp, 8);
        if (q == 0) yo[t*DD] = rndtf(yp + rr.xo * dsk);
    };

    #pragma unroll
    for (int j = 0; j < 8; j++) LDR(j, r[j]);
    for (int t = 0; t < LL; t += 8) {
        #pragma unroll
        for (int j = 0; j < 8; j++) {
            STEP(t + j, r[j]);
            if (t + j + 8 < LL) LDR(t + j + 8, r[j]);
        }
    }
}

__global__ __launch_bounds__(128) void scan_k(const float* __restrict__ x_in,
                                              const float* __restrict__ Dskip)
{
    int b  = blockIdx.y;
    int dl = threadIdx.x >> 4;       // 0..7
    int q  = threadIdx.x & 15;       // 0..15
    int dg = blockIdx.x * 8 + dl;
    float dsk = Dskip[dg];
    float Areg[4] = {0.f, 0.f, 0.f, 0.f};
    bool uni = (g_uniform != 0);
    if (!uni) {
        #pragma unroll
        for (int i = 0; i < 4; i++) Areg[i] = g_A[dg*NN + q*4 + i];
    }
    if (uni) scan_impl<true >(b, dg, q, x_in, dsk, Areg);
    else     scan_impl<false>(b, dg, q, x_in, dsk, Areg);
}

// ---------------- launch ----------------
extern "C" void kernel_launch(void* const* d_in, const int* in_sizes, int n_in,
                              void* d_out, int out_size)
{
    (void)in_sizes; (void)n_in; (void)out_size;
    const float* x        = (const float*)d_in[0];
    const float* norm_w   = (const float*)d_in[1];
    const float* Wx       = (const float*)d_in[2];
    const float* dtW      = (const float*)d_in[3];
    const float* dtb      = (const float*)d_in[4];
    const float* A_log    = (const float*)d_in[5];
    const float* Dskip    = (const float*)d_in[6];
    const float* Wout     = (const float*)d_in[7];
    const float* selW     = (const float*)d_in[8];
    const float* selb     = (const float*)d_in[9];
    const float* sel_gate = (const float*)d_in[10];
    const float* impW     = (const float*)d_in[11];
    const float* impb     = (const float*)d_in[12];
    const float* gateW    = (const float*)d_in[13];
    const float* gateb    = (const float*)d_in[14];
    float* out = (float*)d_out;

    float *p_xn0, *p_xn1, *p_xn2, *p_xp, *p_delta, *p_y, *p_part;
    float *p_wWx, *p_wSel, *p_wImp, *p_wDt, *p_wGate, *p_wOut;
    cudaGetSymbolAddress((void**)&p_xn0,  g_xn0);
    cudaGetSymbolAddress((void**)&p_xn1,  g_xn1);
    cudaGetSymbolAddress((void**)&p_xn2,  g_xn2);
    cudaGetSymbolAddress((void**)&p_xp,   g_xp);
    cudaGetSymbolAddress((void**)&p_delta,g_delta);
    cudaGetSymbolAddress((void**)&p_y,    g_y);
    cudaGetSymbolAddress((void**)&p_part, g_part);
    cudaGetSymbolAddress((void**)&p_wWx,  g_wWx);
    cudaGetSymbolAddress((void**)&p_wSel, g_wSel);
    cudaGetSymbolAddress((void**)&p_wImp, g_wImp);
    cudaGetSymbolAddress((void**)&p_wDt,  g_wDt);
    cudaGetSymbolAddress((void**)&p_wGate,g_wGate);
    cudaGetSymbolAddress((void**)&p_wOut, g_wOut);

    // merged rmsnorm + prep (A matrix + tf32 weight roundings) in one launch
    prerms_k<<<MROWS + 148, 256>>>(x, norm_w, A_log, Wx, selW, impW, dtW, gateW, Wout);

    // merged G1+G2: xp (3 n-blocks) + xn1 (16 n-blocks) in one 304-CTA launch
    gemm12_k<<<dim3(16, 19), GT>>>(p_xn0, p_wWx, p_wSel, p_xp, p_xn1,
                                   selb, sel_gate);
    // merged G5+G4+G3: xn2 (16) + delta (16) + imp split-K partials (8) = 640 CTAs
    gemm345_k<<<dim3(16, 40), GT>>>(p_xn1, p_xp, p_wGate, p_wDt, p_wImp,
                                    p_xn2, p_delta, p_part, gateb, dtb);
    // reduce + sigmoid + fused BC scaling
    bcred_k<<<(MROWS*NN)/256, 256>>>(impb);
    // selective scan -> g_y = round_tf32(y + x*Dskip)
    scan_k<<<dim3(DD/8, BB), 128>>>(x, Dskip);
    // G6: out = g_y @ Wout^T
    gemm6_k<<<dim3(16, 16), GT>>>(p_y, p_wOut, out);
}